// round 1
// baseline (speedup 1.0000x reference)
#include <cuda_runtime.h>
#include <cuda_bf16.h>
#include <cstdint>

#define B 128
#define L 1024
#define E 1280
#define E4 (E/4)     // 320
#define H 128
#define NCH 16       // L-chunks for pooling
#define CHROWS (L/NCH) // 64

// ---------------- scratch (device globals; no allocation allowed) -------------
__device__ float g_pool_part[B * NCH * E];      // 2.62M floats
__device__ float g_xpool[B * E];                // pooled mean
__device__ float g_h[B * 2560];                 // hidden (reused)
__device__ float g_P[4 * B * 2560];             // split-K partials (max 1.31M floats)
__device__ float g_cross[B * 1280];             // standardized concat
__device__ float g_t[B * 1024];                 // feat-encoder hidden
__device__ float g_pf[B * H];                   // pre-LN proj_f

// ---------------- pooling ----------------------------------------------------
__global__ void pool_partial_kernel(const float* __restrict__ esm,
                                    const int* __restrict__ vlens) {
    int b = blockIdx.x;
    int c = blockIdx.y;
    int t = threadIdx.x;            // 320 threads, one float4 each
    int len = vlens[b] + 2;
    int r0 = c * CHROWS;
    int r1 = min(r0 + CHROWS, len);
    float4 s = make_float4(0.f, 0.f, 0.f, 0.f);
    const float4* base = (const float4*)(esm + (size_t)b * L * E);
    for (int r = r0; r < r1; ++r) {
        float4 v = base[(size_t)r * E4 + t];
        s.x += v.x; s.y += v.y; s.z += v.z; s.w += v.w;
    }
    ((float4*)g_pool_part)[((size_t)b * NCH + c) * E4 + t] = s;
}

__global__ void pool_reduce_kernel(const int* __restrict__ vlens) {
    int b = blockIdx.x;
    int t = threadIdx.x;            // 320 threads
    float inv = 1.0f / (float)(vlens[b] + 2);
    float4 s = make_float4(0.f, 0.f, 0.f, 0.f);
    for (int c = 0; c < NCH; ++c) {
        float4 v = ((const float4*)g_pool_part)[((size_t)b * NCH + c) * E4 + t];
        s.x += v.x; s.y += v.y; s.z += v.z; s.w += v.w;
    }
    s.x *= inv; s.y *= inv; s.z *= inv; s.w *= inv;
    ((float4*)g_xpool)[(size_t)b * E4 + t] = s;
}

// ---------------- split-K fp32 GEMM ------------------------------------------
// C_partial[ks][128][N] for K-chunk Kc.  BM=128 (whole M), BN=32, BK=16.
// 128 threads: ty=tid/8 (16), tx=tid%8 (8); thread tile 8 rows x 4 cols.
__global__ __launch_bounds__(128) void gemm_partial_kernel(
    const float* __restrict__ A,   // [128, K] row-major
    const float* __restrict__ W,   // [K, N] row-major
    float* __restrict__ P,         // [ksplit, 128, N]
    int N, int K, int Kc)
{
    __shared__ float As[16][128];
    __shared__ float Bs[16][32];
    int tid = threadIdx.x;
    int n0 = blockIdx.x * 32;
    int k0 = blockIdx.y * Kc;
    int ty = tid >> 3;
    int tx = tid & 7;

    float acc[8][4];
    #pragma unroll
    for (int i = 0; i < 8; ++i)
        #pragma unroll
        for (int j = 0; j < 4; ++j) acc[i][j] = 0.f;

    for (int kt = k0; kt < k0 + Kc; kt += 16) {
        // A tile: thread tid loads row=tid, 16 consecutive floats
        const float* arow = A + (size_t)tid * K + kt;
        float4 a0 = *(const float4*)(arow + 0);
        float4 a1 = *(const float4*)(arow + 4);
        float4 a2 = *(const float4*)(arow + 8);
        float4 a3 = *(const float4*)(arow + 12);
        // B tile: 16x32 floats = 128 float4, one per thread
        int bk = tid >> 3;
        int bc = (tid & 7) * 4;
        float4 bv = *(const float4*)(W + (size_t)(kt + bk) * N + n0 + bc);

        __syncthreads();   // protect previous iteration's reads
        float av[16] = {a0.x,a0.y,a0.z,a0.w, a1.x,a1.y,a1.z,a1.w,
                        a2.x,a2.y,a2.z,a2.w, a3.x,a3.y,a3.z,a3.w};
        #pragma unroll
        for (int kk = 0; kk < 16; ++kk) As[kk][tid] = av[kk];
        *(float4*)&Bs[bk][bc] = bv;
        __syncthreads();

        #pragma unroll
        for (int kk = 0; kk < 16; ++kk) {
            float4 x0 = *(const float4*)&As[kk][ty * 8];
            float4 x1 = *(const float4*)&As[kk][ty * 8 + 4];
            float4 bb = *(const float4*)&Bs[kk][tx * 4];
            float am[8] = {x0.x,x0.y,x0.z,x0.w, x1.x,x1.y,x1.z,x1.w};
            float bn[4] = {bb.x,bb.y,bb.z,bb.w};
            #pragma unroll
            for (int i = 0; i < 8; ++i)
                #pragma unroll
                for (int j = 0; j < 4; ++j)
                    acc[i][j] = fmaf(am[i], bn[j], acc[i][j]);
        }
    }

    float* p = P + ((size_t)blockIdx.y * 128) * N + n0;
    #pragma unroll
    for (int i = 0; i < 8; ++i) {
        int m = ty * 8 + i;
        float4 o = make_float4(acc[i][0], acc[i][1], acc[i][2], acc[i][3]);
        *(float4*)(p + (size_t)m * N + tx * 4) = o;
    }
}

__global__ void gemm_reduce_kernel(const float* __restrict__ P,
                                   const float* __restrict__ bias,
                                   float* __restrict__ out,
                                   int MN, int N, int ksplit, int relu)
{
    int i = blockIdx.x * 256 + threadIdx.x;
    if (i >= MN) return;
    float s = bias ? bias[i % N] : 0.f;
    for (int ks = 0; ks < ksplit; ++ks) s += P[(size_t)ks * MN + i];
    if (relu) s = fmaxf(s, 0.f);
    out[i] = s;
}

// ---------------- standardize (batch dim, ddof=1) ----------------------------
__device__ __forceinline__ float block_reduce_128(float v, float* sh) {
    int t = threadIdx.x;
    sh[t] = v;
    __syncthreads();
    #pragma unroll
    for (int s = 64; s > 0; s >>= 1) {
        if (t < s) sh[t] += sh[t + s];
        __syncthreads();
    }
    float r = sh[0];
    __syncthreads();
    return r;
}

__global__ void standardize_col_kernel(const float* __restrict__ in,
                                       float* __restrict__ out,
                                       int ncol_in, int ncol_out, int col_off)
{
    __shared__ float sh[128];
    int col = blockIdx.x;
    int t = threadIdx.x;    // 128 threads = B rows
    float v = in[(size_t)t * ncol_in + col];
    float mean = block_reduce_128(v, sh) * (1.0f / 128.0f);
    float d = v - mean;
    float var = block_reduce_128(d * d, sh) * (1.0f / 127.0f);  // ddof=1
    out[(size_t)t * ncol_out + col_off + col] = d * rsqrtf(var);
}

// ---------------- layernorm (last dim, ddof=0, eps) ---------------------------
__global__ void layernorm_row_kernel(const float* __restrict__ in,
                                     const float* __restrict__ g,
                                     const float* __restrict__ bta,
                                     float* __restrict__ out)
{
    __shared__ float sh[128];
    int row = blockIdx.x;
    int t = threadIdx.x;    // 128 threads = H
    float v = in[(size_t)row * H + t];
    float mean = block_reduce_128(v, sh) * (1.0f / 128.0f);
    float d = v - mean;
    float var = block_reduce_128(d * d, sh) * (1.0f / 128.0f);
    out[(size_t)row * H + t] = d * rsqrtf(var + 1e-5f) * g[t] + bta[t];
}

// ---------------- launch ------------------------------------------------------
extern "C" void kernel_launch(void* const* d_in, const int* in_sizes, int n_in,
                              void* d_out, int out_size)
{
    const float* esm      = (const float*)d_in[0];
    const int*   vlens    = (const int*)  d_in[1];
    const float* modal_a  = (const float*)d_in[2];
    const float* modal_b  = (const float*)d_in[3];
    const float* layer_w1 = (const float*)d_in[4];
    const float* layer_b1 = (const float*)d_in[5];
    const float* layer_w2 = (const float*)d_in[6];
    const float* layer_b2 = (const float*)d_in[7];
    const float* mlp_w1   = (const float*)d_in[8];
    const float* mlp_b1   = (const float*)d_in[9];
    const float* mlp_w2   = (const float*)d_in[10];
    const float* mlp_b2   = (const float*)d_in[11];
    const float* fe_w1    = (const float*)d_in[12];
    const float* fe_w2    = (const float*)d_in[13];
    const float* fe_b2    = (const float*)d_in[14];
    const float* lnf_g    = (const float*)d_in[15];
    const float* lnf_b    = (const float*)d_in[16];

    float* out_x  = (float*)d_out;                 // [128,1280]
    float* out_px = out_x + B * E;                 // [128,128]
    float* out_pf = out_px + B * H;                // [128,128]

    float* xpool = nullptr; cudaGetSymbolAddress((void**)&xpool, g_xpool);
    float* hbuf  = nullptr; cudaGetSymbolAddress((void**)&hbuf,  g_h);
    float* Pbuf  = nullptr; cudaGetSymbolAddress((void**)&Pbuf,  g_P);
    float* cross = nullptr; cudaGetSymbolAddress((void**)&cross, g_cross);
    float* tbuf  = nullptr; cudaGetSymbolAddress((void**)&tbuf,  g_t);
    float* pfbuf = nullptr; cudaGetSymbolAddress((void**)&pfbuf, g_pf);

    // 1) ragged mean pool
    pool_partial_kernel<<<dim3(B, NCH), 320>>>(esm, vlens);
    pool_reduce_kernel<<<B, 320>>>(vlens);

    // 2) layers: relu(x@W1+b1)@W2+b2 -> out_x
    gemm_partial_kernel<<<dim3(2560/32, 4), 128>>>(xpool, layer_w1, Pbuf, 2560, 1280, 320);
    gemm_reduce_kernel<<<(B*2560+255)/256, 256>>>(Pbuf, layer_b1, hbuf, B*2560, 2560, 4, 1);
    gemm_partial_kernel<<<dim3(1280/32, 8), 128>>>(hbuf, layer_w2, Pbuf, 1280, 2560, 320);
    gemm_reduce_kernel<<<(B*1280+255)/256, 256>>>(Pbuf, layer_b2, out_x, B*1280, 1280, 8, 0);

    // 3) mlp: relu(x@W1+b1)@W2+b2 -> out_px
    gemm_partial_kernel<<<dim3(2560/32, 4), 128>>>(out_x, mlp_w1, Pbuf, 2560, 1280, 320);
    gemm_reduce_kernel<<<(B*2560+255)/256, 256>>>(Pbuf, mlp_b1, hbuf, B*2560, 2560, 4, 1);
    gemm_partial_kernel<<<dim3(128/32, 32), 128>>>(hbuf, mlp_w2, Pbuf, 128, 2560, 80);
    gemm_reduce_kernel<<<(B*128+255)/256, 256>>>(Pbuf, mlp_b2, out_px, B*128, 128, 32, 0);

    // 4) multimodal: standardize a, b -> concat; standardize again (in-place)
    standardize_col_kernel<<<512, 128>>>(modal_a, cross, 512, 1280, 0);
    standardize_col_kernel<<<768, 128>>>(modal_b, cross, 768, 1280, 512);
    standardize_col_kernel<<<1280, 128>>>(cross, cross, 1280, 1280, 0);

    // 5) feat_encoder: relu(cross@fe_w1)@fe_w2 + fe_b2, then layernorm
    gemm_partial_kernel<<<dim3(1024/32, 8), 128>>>(cross, fe_w1, Pbuf, 1024, 1280, 160);
    gemm_reduce_kernel<<<(B*1024+255)/256, 256>>>(Pbuf, nullptr, tbuf, B*1024, 1024, 8, 1);
    gemm_partial_kernel<<<dim3(128/32, 16), 128>>>(tbuf, fe_w2, Pbuf, 128, 1024, 64);
    gemm_reduce_kernel<<<(B*128+255)/256, 256>>>(Pbuf, fe_b2, pfbuf, B*128, 128, 16, 0);
    layernorm_row_kernel<<<B, 128>>>(pfbuf, lnf_g, lnf_b, out_pf);
}

// round 2
// speedup vs baseline: 1.0030x; 1.0030x over previous
#include <cuda_runtime.h>
#include <cuda_bf16.h>
#include <cstdint>

#define B 128
#define L 1024
#define E 1280
#define E4 (E/4)     // 320
#define H 128
#define NCH 16       // L-chunks for pooling
#define CHROWS (L/NCH) // 64

// ---------------- scratch (device globals; no allocation allowed) -------------
__device__ float g_pool_part[B * NCH * E];
__device__ float g_xpool[B * E];
__device__ float g_h[B * 2560];
__device__ float g_P[4 * B * 2560];
__device__ float g_cross[B * 1280];
__device__ float g_t[B * 1024];
__device__ float g_pf[B * H];

// ---------------- pooling ----------------------------------------------------
__global__ void pool_partial_kernel(const float* __restrict__ esm,
                                    const int* __restrict__ vlens) {
    int b = blockIdx.x;
    int c = blockIdx.y;
    int t = threadIdx.x;            // 320 threads, one float4 each
    int len = vlens[b] + 2;
    int r0 = c * CHROWS;
    int r1 = min(r0 + CHROWS, len);
    float4 s = make_float4(0.f, 0.f, 0.f, 0.f);
    const float4* base = (const float4*)(esm + (size_t)b * L * E);
    for (int r = r0; r < r1; ++r) {
        float4 v = base[(size_t)r * E4 + t];
        s.x += v.x; s.y += v.y; s.z += v.z; s.w += v.w;
    }
    ((float4*)g_pool_part)[((size_t)b * NCH + c) * E4 + t] = s;
}

__global__ void pool_reduce_kernel(const int* __restrict__ vlens) {
    int b = blockIdx.x;
    int t = threadIdx.x;            // 320 threads
    float inv = 1.0f / (float)(vlens[b] + 2);
    float4 s = make_float4(0.f, 0.f, 0.f, 0.f);
    for (int c = 0; c < NCH; ++c) {
        float4 v = ((const float4*)g_pool_part)[((size_t)b * NCH + c) * E4 + t];
        s.x += v.x; s.y += v.y; s.z += v.z; s.w += v.w;
    }
    s.x *= inv; s.y *= inv; s.z *= inv; s.w *= inv;
    ((float4*)g_xpool)[(size_t)b * E4 + t] = s;
}

// ---------------- tf32 tensor-core GEMM --------------------------------------
// C[128, N] (+= over optional split-K) = A[128, K] @ W[K, N]
// BM=128, BN=32, BK=32. 256 threads = 8 warps laid out 4(m) x 2(n).
// Warp tile 32x16 -> 2x2 m16n8k8 mma tiles. fp32 accumulate, tf32 inputs (RNA).
__device__ __forceinline__ unsigned f2tf(float x) {
    unsigned r; asm("cvt.rna.tf32.f32 %0, %1;" : "=r"(r) : "f"(x)); return r;
}

__global__ __launch_bounds__(256) void gemm_tc_kernel(
    const float* __restrict__ A, const float* __restrict__ W,
    float* __restrict__ out, float* __restrict__ P,
    const float* __restrict__ bias,
    int N, int K, int Kc, int relu, int ksplit)
{
    __shared__ unsigned As[128 * 36];     // row-major, stride 36 (pad 4)
    __shared__ unsigned Bs[4 * 32 * 8];   // [n-chunk][k][8]

    int tid = threadIdx.x;
    int warp = tid >> 5;
    int lane = tid & 31;
    int wm = warp >> 1;       // 0..3 (m)
    int wn = warp & 1;        // 0..1 (n)
    int g  = lane >> 2;       // 0..7
    int tg = lane & 3;        // 0..3

    int n_blk = blockIdx.x * 32;
    int k0 = blockIdx.y * Kc;

    float acc[2][2][4];
    #pragma unroll
    for (int mt = 0; mt < 2; ++mt)
        #pragma unroll
        for (int nt = 0; nt < 2; ++nt)
            #pragma unroll
            for (int i = 0; i < 4; ++i) acc[mt][nt][i] = 0.f;

    int arow0 = tid >> 3;          // base row for A loads (j adds 32)
    int akq   = (tid & 7) * 4;     // k offset within tile
    int wk    = tid >> 3;          // k row for W load
    int wn4   = (tid & 7) * 4;     // n offset within tile
    int wchunk = wn4 >> 3;
    int woff   = wn4 & 7;

    for (int kt = k0; kt < k0 + Kc; kt += 32) {
        // stage gmem loads in registers
        float4 av[4];
        #pragma unroll
        for (int j = 0; j < 4; ++j) {
            int row = arow0 + 32 * j;
            av[j] = *(const float4*)(A + (size_t)row * K + kt + akq);
        }
        float4 wv = *(const float4*)(W + (size_t)(kt + wk) * N + n_blk + wn4);

        __syncthreads();   // previous iteration's smem reads done
        #pragma unroll
        for (int j = 0; j < 4; ++j) {
            int row = arow0 + 32 * j;
            unsigned* ap = &As[row * 36 + akq];
            ap[0] = f2tf(av[j].x); ap[1] = f2tf(av[j].y);
            ap[2] = f2tf(av[j].z); ap[3] = f2tf(av[j].w);
        }
        {
            unsigned* bp = &Bs[wchunk * 256 + wk * 8 + woff];
            bp[0] = f2tf(wv.x); bp[1] = f2tf(wv.y);
            bp[2] = f2tf(wv.z); bp[3] = f2tf(wv.w);
        }
        __syncthreads();

        #pragma unroll
        for (int ks = 0; ks < 4; ++ks) {
            int k = ks * 8;
            unsigned a[2][4], bf[2][2];
            #pragma unroll
            for (int mt = 0; mt < 2; ++mt) {
                int r = wm * 32 + mt * 16 + g;
                a[mt][0] = As[r * 36 + k + tg];
                a[mt][1] = As[(r + 8) * 36 + k + tg];
                a[mt][2] = As[r * 36 + k + tg + 4];
                a[mt][3] = As[(r + 8) * 36 + k + tg + 4];
            }
            #pragma unroll
            for (int nt = 0; nt < 2; ++nt) {
                int c = wn * 2 + nt;
                bf[nt][0] = Bs[c * 256 + (k + tg) * 8 + g];
                bf[nt][1] = Bs[c * 256 + (k + tg + 4) * 8 + g];
            }
            #pragma unroll
            for (int mt = 0; mt < 2; ++mt)
                #pragma unroll
                for (int nt = 0; nt < 2; ++nt) {
                    asm volatile(
                        "mma.sync.aligned.m16n8k8.row.col.f32.tf32.tf32.f32 "
                        "{%0,%1,%2,%3}, {%4,%5,%6,%7}, {%8,%9}, {%0,%1,%2,%3};\n"
                        : "+f"(acc[mt][nt][0]), "+f"(acc[mt][nt][1]),
                          "+f"(acc[mt][nt][2]), "+f"(acc[mt][nt][3])
                        : "r"(a[mt][0]), "r"(a[mt][1]), "r"(a[mt][2]), "r"(a[mt][3]),
                          "r"(bf[nt][0]), "r"(bf[nt][1]));
                }
        }
    }

    // epilogue
    if (ksplit == 1) {
        #pragma unroll
        for (int mt = 0; mt < 2; ++mt) {
            int row = wm * 32 + mt * 16 + g;
            #pragma unroll
            for (int nt = 0; nt < 2; ++nt) {
                int nglob = n_blk + wn * 16 + nt * 8 + tg * 2;
                float b0 = bias ? bias[nglob]     : 0.f;
                float b1 = bias ? bias[nglob + 1] : 0.f;
                float v0 = acc[mt][nt][0] + b0;
                float v1 = acc[mt][nt][1] + b1;
                float v2 = acc[mt][nt][2] + b0;
                float v3 = acc[mt][nt][3] + b1;
                if (relu) {
                    v0 = fmaxf(v0, 0.f); v1 = fmaxf(v1, 0.f);
                    v2 = fmaxf(v2, 0.f); v3 = fmaxf(v3, 0.f);
                }
                *(float2*)(out + (size_t)row * N + nglob) = make_float2(v0, v1);
                *(float2*)(out + (size_t)(row + 8) * N + nglob) = make_float2(v2, v3);
            }
        }
    } else {
        float* dst = P + (size_t)blockIdx.y * 128 * N;
        #pragma unroll
        for (int mt = 0; mt < 2; ++mt) {
            int row = wm * 32 + mt * 16 + g;
            #pragma unroll
            for (int nt = 0; nt < 2; ++nt) {
                int nglob = n_blk + wn * 16 + nt * 8 + tg * 2;
                *(float2*)(dst + (size_t)row * N + nglob) =
                    make_float2(acc[mt][nt][0], acc[mt][nt][1]);
                *(float2*)(dst + (size_t)(row + 8) * N + nglob) =
                    make_float2(acc[mt][nt][2], acc[mt][nt][3]);
            }
        }
    }
}

__global__ void gemm_reduce_kernel(const float* __restrict__ P,
                                   const float* __restrict__ bias,
                                   float* __restrict__ out,
                                   int MN, int N, int ksplit, int relu)
{
    int i = blockIdx.x * 256 + threadIdx.x;
    if (i >= MN) return;
    float s = bias ? bias[i % N] : 0.f;
    for (int ks = 0; ks < ksplit; ++ks) s += P[(size_t)ks * MN + i];
    if (relu) s = fmaxf(s, 0.f);
    out[i] = s;
}

// ---------------- standardize (batch dim, ddof=1) ----------------------------
__device__ __forceinline__ float block_reduce_128(float v, float* sh) {
    int t = threadIdx.x;
    sh[t] = v;
    __syncthreads();
    #pragma unroll
    for (int s = 64; s > 0; s >>= 1) {
        if (t < s) sh[t] += sh[t + s];
        __syncthreads();
    }
    float r = sh[0];
    __syncthreads();
    return r;
}

__global__ void standardize_col_kernel(const float* __restrict__ in,
                                       float* __restrict__ out,
                                       int ncol_in, int ncol_out, int col_off)
{
    __shared__ float sh[128];
    int col = blockIdx.x;
    int t = threadIdx.x;    // 128 threads = B rows
    float v = in[(size_t)t * ncol_in + col];
    float mean = block_reduce_128(v, sh) * (1.0f / 128.0f);
    float d = v - mean;
    float var = block_reduce_128(d * d, sh) * (1.0f / 127.0f);  // ddof=1
    out[(size_t)t * ncol_out + col_off + col] = d * rsqrtf(var);
}

// ---------------- layernorm (last dim, ddof=0, eps) ---------------------------
__global__ void layernorm_row_kernel(const float* __restrict__ in,
                                     const float* __restrict__ g,
                                     const float* __restrict__ bta,
                                     float* __restrict__ out)
{
    __shared__ float sh[128];
    int row = blockIdx.x;
    int t = threadIdx.x;    // 128 threads = H
    float v = in[(size_t)row * H + t];
    float mean = block_reduce_128(v, sh) * (1.0f / 128.0f);
    float d = v - mean;
    float var = block_reduce_128(d * d, sh) * (1.0f / 128.0f);
    out[(size_t)row * H + t] = d * rsqrtf(var + 1e-5f) * g[t] + bta[t];
}

// ---------------- launch ------------------------------------------------------
extern "C" void kernel_launch(void* const* d_in, const int* in_sizes, int n_in,
                              void* d_out, int out_size)
{
    const float* esm      = (const float*)d_in[0];
    const int*   vlens    = (const int*)  d_in[1];
    const float* modal_a  = (const float*)d_in[2];
    const float* modal_b  = (const float*)d_in[3];
    const float* layer_w1 = (const float*)d_in[4];
    const float* layer_b1 = (const float*)d_in[5];
    const float* layer_w2 = (const float*)d_in[6];
    const float* layer_b2 = (const float*)d_in[7];
    const float* mlp_w1   = (const float*)d_in[8];
    const float* mlp_b1   = (const float*)d_in[9];
    const float* mlp_w2   = (const float*)d_in[10];
    const float* mlp_b2   = (const float*)d_in[11];
    const float* fe_w1    = (const float*)d_in[12];
    const float* fe_w2    = (const float*)d_in[13];
    const float* fe_b2    = (const float*)d_in[14];
    const float* lnf_g    = (const float*)d_in[15];
    const float* lnf_b    = (const float*)d_in[16];

    float* out_x  = (float*)d_out;                 // [128,1280]
    float* out_px = out_x + B * E;                 // [128,128]
    float* out_pf = out_px + B * H;                // [128,128]

    float* xpool = nullptr; cudaGetSymbolAddress((void**)&xpool, g_xpool);
    float* hbuf  = nullptr; cudaGetSymbolAddress((void**)&hbuf,  g_h);
    float* Pbuf  = nullptr; cudaGetSymbolAddress((void**)&Pbuf,  g_P);
    float* cross = nullptr; cudaGetSymbolAddress((void**)&cross, g_cross);
    float* tbuf  = nullptr; cudaGetSymbolAddress((void**)&tbuf,  g_t);
    float* pfbuf = nullptr; cudaGetSymbolAddress((void**)&pfbuf, g_pf);

    // 1) ragged mean pool
    pool_partial_kernel<<<dim3(B, NCH), 320>>>(esm, vlens);
    pool_reduce_kernel<<<B, 320>>>(vlens);

    // 2) layers: relu(x@W1+b1)@W2+b2 -> out_x
    gemm_tc_kernel<<<dim3(80, 1), 256>>>(xpool, layer_w1, hbuf, Pbuf, layer_b1,
                                         2560, 1280, 1280, 1, 1);
    gemm_tc_kernel<<<dim3(40, 2), 256>>>(hbuf, layer_w2, nullptr, Pbuf, nullptr,
                                         1280, 2560, 1280, 0, 2);
    gemm_reduce_kernel<<<(B*1280+255)/256, 256>>>(Pbuf, layer_b2, out_x, B*1280, 1280, 2, 0);

    // 3) mlp: relu(x@W1+b1)@W2+b2 -> out_px
    gemm_tc_kernel<<<dim3(80, 1), 256>>>(out_x, mlp_w1, hbuf, Pbuf, mlp_b1,
                                         2560, 1280, 1280, 1, 1);
    gemm_tc_kernel<<<dim3(4, 16), 256>>>(hbuf, mlp_w2, nullptr, Pbuf, nullptr,
                                         128, 2560, 160, 0, 16);
    gemm_reduce_kernel<<<(B*128+255)/256, 256>>>(Pbuf, mlp_b2, out_px, B*128, 128, 16, 0);

    // 4) multimodal: standardize a, b -> concat; standardize again
    standardize_col_kernel<<<512, 128>>>(modal_a, cross, 512, 1280, 0);
    standardize_col_kernel<<<768, 128>>>(modal_b, cross, 768, 1280, 512);
    standardize_col_kernel<<<1280, 128>>>(cross, cross, 1280, 1280, 0);

    // 5) feat_encoder: relu(cross@fe_w1)@fe_w2 + fe_b2, then layernorm
    gemm_tc_kernel<<<dim3(32, 4), 256>>>(cross, fe_w1, nullptr, Pbuf, nullptr,
                                         1024, 1280, 320, 0, 4);
    gemm_reduce_kernel<<<(B*1024+255)/256, 256>>>(Pbuf, nullptr, tbuf, B*1024, 1024, 4, 1);
    gemm_tc_kernel<<<dim3(4, 8), 256>>>(tbuf, fe_w2, nullptr, Pbuf, nullptr,
                                        128, 1024, 128, 0, 8);
    gemm_reduce_kernel<<<(B*128+255)/256, 256>>>(Pbuf, fe_b2, pfbuf, B*128, 128, 8, 0);
    layernorm_row_kernel<<<B, 128>>>(pfbuf, lnf_g, lnf_b, out_pf);
}

// round 3
// speedup vs baseline: 1.4375x; 1.4331x over previous
#include <cuda_runtime.h>
#include <cuda_bf16.h>
#include <cstdint>

#define B 128
#define L 1024
#define E 1280
#define E4 (E/4)     // 320
#define H 128
#define NCH 16
#define CHROWS (L/NCH) // 64

// ---------------- scratch ------------------------------------------------------
__device__ float g_pool_part[B * NCH * E];
__device__ float g_xpool[B * E];
__device__ float g_h[B * 2560];
__device__ float g_P[16 * B * 2560 / 4];   // split-K partials (max 16*128*128? use 4*B*2560)
__device__ float g_cross[B * 1280];
__device__ float g_t[B * 1024];

// ---------------- pooling ----------------------------------------------------
__global__ void pool_partial_kernel(const float* __restrict__ esm,
                                    const int* __restrict__ vlens) {
    int b = blockIdx.x;
    int c = blockIdx.y;
    int t = threadIdx.x;            // 320 threads, one float4 each
    int len = vlens[b] + 2;
    int r0 = c * CHROWS;
    int r1 = min(r0 + CHROWS, len);
    float4 s = make_float4(0.f, 0.f, 0.f, 0.f);
    const float4* base = (const float4*)(esm + (size_t)b * L * E);
    for (int r = r0; r < r1; ++r) {
        float4 v = base[(size_t)r * E4 + t];
        s.x += v.x; s.y += v.y; s.z += v.z; s.w += v.w;
    }
    ((float4*)g_pool_part)[((size_t)b * NCH + c) * E4 + t] = s;
}

__global__ void pool_reduce_kernel(const int* __restrict__ vlens) {
    int b = blockIdx.x;
    int t = threadIdx.x;            // 320 threads
    float inv = 1.0f / (float)(vlens[b] + 2);
    float4 s = make_float4(0.f, 0.f, 0.f, 0.f);
    for (int c = 0; c < NCH; ++c) {
        float4 v = ((const float4*)g_pool_part)[((size_t)b * NCH + c) * E4 + t];
        s.x += v.x; s.y += v.y; s.z += v.z; s.w += v.w;
    }
    s.x *= inv; s.y *= inv; s.z *= inv; s.w *= inv;
    ((float4*)g_xpool)[(size_t)b * E4 + t] = s;
}

// ---------------- tf32 tensor-core GEMM, double-buffered ----------------------
// P[ks][128][N] partial = A[128, k0:k0+Kc] @ W[k0:k0+Kc, N] for K-chunk.
// BM=128, BN=32, BK=32. 256 threads = 8 warps (4m x 2n). Warp tile 32x16.
__device__ __forceinline__ unsigned f2tf(float x) {
    unsigned r; asm("cvt.rna.tf32.f32 %0, %1;" : "=r"(r) : "f"(x)); return r;
}

__global__ __launch_bounds__(256, 2) void gemm_tc_kernel(
    const float* __restrict__ A, const float* __restrict__ W,
    float* __restrict__ P, int N, int K, int Kc)
{
    __shared__ unsigned As[2][128 * 36];
    __shared__ unsigned Bs[2][4 * 32 * 8];

    int tid = threadIdx.x;
    int warp = tid >> 5;
    int lane = tid & 31;
    int wm = warp >> 1;
    int wn = warp & 1;
    int g  = lane >> 2;
    int tg = lane & 3;

    int n_blk = blockIdx.x * 32;
    int k0 = blockIdx.y * Kc;

    int arow0 = tid >> 3;
    int akq   = (tid & 7) * 4;
    int wk    = tid >> 3;
    int wn4   = (tid & 7) * 4;
    int wchunk = wn4 >> 3;
    int woff   = wn4 & 7;

    float acc[2][2][4];
    #pragma unroll
    for (int mt = 0; mt < 2; ++mt)
        #pragma unroll
        for (int nt = 0; nt < 2; ++nt)
            #pragma unroll
            for (int i = 0; i < 4; ++i) acc[mt][nt][i] = 0.f;

    float4 av[4]; float4 wv;

    // prologue: load + store tile 0
    #pragma unroll
    for (int j = 0; j < 4; ++j)
        av[j] = *(const float4*)(A + (size_t)(arow0 + 32 * j) * K + k0 + akq);
    wv = *(const float4*)(W + (size_t)(k0 + wk) * N + n_blk + wn4);
    #pragma unroll
    for (int j = 0; j < 4; ++j) {
        unsigned* ap = &As[0][(arow0 + 32 * j) * 36 + akq];
        ap[0] = f2tf(av[j].x); ap[1] = f2tf(av[j].y);
        ap[2] = f2tf(av[j].z); ap[3] = f2tf(av[j].w);
    }
    {
        unsigned* bp = &Bs[0][wchunk * 256 + wk * 8 + woff];
        bp[0] = f2tf(wv.x); bp[1] = f2tf(wv.y);
        bp[2] = f2tf(wv.z); bp[3] = f2tf(wv.w);
    }

    int niter = Kc >> 5;
    int buf = 0;
    for (int it = 0; it < niter; ++it) {
        __syncthreads();
        bool has_next = (it + 1 < niter);
        if (has_next) {
            int kt = k0 + (it + 1) * 32;
            #pragma unroll
            for (int j = 0; j < 4; ++j)
                av[j] = *(const float4*)(A + (size_t)(arow0 + 32 * j) * K + kt + akq);
            wv = *(const float4*)(W + (size_t)(kt + wk) * N + n_blk + wn4);
        }

        const unsigned* Ab = As[buf];
        const unsigned* Bb = Bs[buf];
        #pragma unroll
        for (int ks = 0; ks < 4; ++ks) {
            int k = ks * 8;
            unsigned a[2][4], bf[2][2];
            #pragma unroll
            for (int mt = 0; mt < 2; ++mt) {
                int r = wm * 32 + mt * 16 + g;
                a[mt][0] = Ab[r * 36 + k + tg];
                a[mt][1] = Ab[(r + 8) * 36 + k + tg];
                a[mt][2] = Ab[r * 36 + k + tg + 4];
                a[mt][3] = Ab[(r + 8) * 36 + k + tg + 4];
            }
            #pragma unroll
            for (int nt = 0; nt < 2; ++nt) {
                int c = wn * 2 + nt;
                bf[nt][0] = Bb[c * 256 + (k + tg) * 8 + g];
                bf[nt][1] = Bb[c * 256 + (k + tg + 4) * 8 + g];
            }
            #pragma unroll
            for (int mt = 0; mt < 2; ++mt)
                #pragma unroll
                for (int nt = 0; nt < 2; ++nt) {
                    asm volatile(
                        "mma.sync.aligned.m16n8k8.row.col.f32.tf32.tf32.f32 "
                        "{%0,%1,%2,%3}, {%4,%5,%6,%7}, {%8,%9}, {%0,%1,%2,%3};\n"
                        : "+f"(acc[mt][nt][0]), "+f"(acc[mt][nt][1]),
                          "+f"(acc[mt][nt][2]), "+f"(acc[mt][nt][3])
                        : "r"(a[mt][0]), "r"(a[mt][1]), "r"(a[mt][2]), "r"(a[mt][3]),
                          "r"(bf[nt][0]), "r"(bf[nt][1]));
                }
        }

        if (has_next) {
            unsigned* Aw = As[buf ^ 1];
            unsigned* Bw = Bs[buf ^ 1];
            #pragma unroll
            for (int j = 0; j < 4; ++j) {
                unsigned* ap = &Aw[(arow0 + 32 * j) * 36 + akq];
                ap[0] = f2tf(av[j].x); ap[1] = f2tf(av[j].y);
                ap[2] = f2tf(av[j].z); ap[3] = f2tf(av[j].w);
            }
            unsigned* bp = &Bw[wchunk * 256 + wk * 8 + woff];
            bp[0] = f2tf(wv.x); bp[1] = f2tf(wv.y);
            bp[2] = f2tf(wv.z); bp[3] = f2tf(wv.w);
        }
        buf ^= 1;
    }

    float* dst = P + (size_t)blockIdx.y * 128 * N + n_blk;
    #pragma unroll
    for (int mt = 0; mt < 2; ++mt) {
        int row = wm * 32 + mt * 16 + g;
        #pragma unroll
        for (int nt = 0; nt < 2; ++nt) {
            int nloc = wn * 16 + nt * 8 + tg * 2;
            *(float2*)(dst + (size_t)row * N + nloc) =
                make_float2(acc[mt][nt][0], acc[mt][nt][1]);
            *(float2*)(dst + (size_t)(row + 8) * N + nloc) =
                make_float2(acc[mt][nt][2], acc[mt][nt][3]);
        }
    }
}

// ---------------- split-K reduce (float4) ------------------------------------
__global__ void gemm_reduce_kernel(const float* __restrict__ P,
                                   const float* __restrict__ bias,
                                   float* __restrict__ out,
                                   int MN4, int N4, int ksplit, int relu)
{
    int i = blockIdx.x * 256 + threadIdx.x;
    if (i >= MN4) return;
    float4 s;
    if (bias) s = ((const float4*)bias)[i % N4];
    else      s = make_float4(0.f, 0.f, 0.f, 0.f);
    for (int ks = 0; ks < ksplit; ++ks) {
        float4 v = ((const float4*)P)[(size_t)ks * MN4 + i];
        s.x += v.x; s.y += v.y; s.z += v.z; s.w += v.w;
    }
    if (relu) {
        s.x = fmaxf(s.x, 0.f); s.y = fmaxf(s.y, 0.f);
        s.z = fmaxf(s.z, 0.f); s.w = fmaxf(s.w, 0.f);
    }
    ((float4*)out)[i] = s;
}

// ---------------- block reduce helper -----------------------------------------
__device__ __forceinline__ float block_reduce_128(float v, float* sh) {
    int t = threadIdx.x;
    sh[t] = v;
    __syncthreads();
    #pragma unroll
    for (int s = 64; s > 0; s >>= 1) {
        if (t < s) sh[t] += sh[t + s];
        __syncthreads();
    }
    float r = sh[0];
    __syncthreads();
    return r;
}

// ---------------- fused standardize of modal_a | modal_b ----------------------
// (second standardize of the concat is the exact identity: each column already
//  has mean 0 and ddof-1 std 1, so it is skipped.)
__global__ void std_ab_kernel(const float* __restrict__ a,
                              const float* __restrict__ bsrc,
                              float* __restrict__ cross)
{
    __shared__ float sh[128];
    int col = blockIdx.x;           // 0..1279
    int t = threadIdx.x;            // 128 rows
    const float* src; int nc, c;
    if (col < 512) { src = a;    nc = 512; c = col; }
    else           { src = bsrc; nc = 768; c = col - 512; }
    float v = src[(size_t)t * nc + c];
    float mean = block_reduce_128(v, sh) * (1.0f / 128.0f);
    float d = v - mean;
    float var = block_reduce_128(d * d, sh) * (1.0f / 127.0f);  // ddof=1
    cross[(size_t)t * 1280 + col] = d * rsqrtf(var);
}

// ---------------- fused split-K reduce + bias + layernorm ---------------------
__global__ void reduce_ln_kernel(const float* __restrict__ P,
                                 const float* __restrict__ bias,
                                 const float* __restrict__ g,
                                 const float* __restrict__ bta,
                                 float* __restrict__ out, int ksplit)
{
    __shared__ float sh[128];
    int row = blockIdx.x;
    int t = threadIdx.x;            // H = 128 cols
    float s = bias[t];
    for (int ks = 0; ks < ksplit; ++ks)
        s += P[(size_t)ks * (B * H) + (size_t)row * H + t];
    float mean = block_reduce_128(s, sh) * (1.0f / 128.0f);
    float d = s - mean;
    float var = block_reduce_128(d * d, sh) * (1.0f / 128.0f);
    out[(size_t)row * H + t] = d * rsqrtf(var + 1e-5f) * g[t] + bta[t];
}

// ---------------- launch ------------------------------------------------------
extern "C" void kernel_launch(void* const* d_in, const int* in_sizes, int n_in,
                              void* d_out, int out_size)
{
    const float* esm      = (const float*)d_in[0];
    const int*   vlens    = (const int*)  d_in[1];
    const float* modal_a  = (const float*)d_in[2];
    const float* modal_b  = (const float*)d_in[3];
    const float* layer_w1 = (const float*)d_in[4];
    const float* layer_b1 = (const float*)d_in[5];
    const float* layer_w2 = (const float*)d_in[6];
    const float* layer_b2 = (const float*)d_in[7];
    const float* mlp_w1   = (const float*)d_in[8];
    const float* mlp_b1   = (const float*)d_in[9];
    const float* mlp_w2   = (const float*)d_in[10];
    const float* mlp_b2   = (const float*)d_in[11];
    const float* fe_w1    = (const float*)d_in[12];
    const float* fe_w2    = (const float*)d_in[13];
    const float* fe_b2    = (const float*)d_in[14];
    const float* lnf_g    = (const float*)d_in[15];
    const float* lnf_b    = (const float*)d_in[16];

    float* out_x  = (float*)d_out;
    float* out_px = out_x + B * E;
    float* out_pf = out_px + B * H;

    float* xpool = nullptr; cudaGetSymbolAddress((void**)&xpool, g_xpool);
    float* hbuf  = nullptr; cudaGetSymbolAddress((void**)&hbuf,  g_h);
    float* Pbuf  = nullptr; cudaGetSymbolAddress((void**)&Pbuf,  g_P);
    float* cross = nullptr; cudaGetSymbolAddress((void**)&cross, g_cross);
    float* tbuf  = nullptr; cudaGetSymbolAddress((void**)&tbuf,  g_t);

    // 1) ragged mean pool
    pool_partial_kernel<<<dim3(B, NCH), 320>>>(esm, vlens);
    pool_reduce_kernel<<<B, 320>>>(vlens);

    // 2) layers: relu(x@W1+b1)@W2+b2 -> out_x
    gemm_tc_kernel<<<dim3(80, 4), 256>>>(xpool, layer_w1, Pbuf, 2560, 1280, 320);
    gemm_reduce_kernel<<<(B*2560/4+255)/256, 256>>>(Pbuf, layer_b1, hbuf, B*2560/4, 2560/4, 4, 1);
    gemm_tc_kernel<<<dim3(40, 8), 256>>>(hbuf, layer_w2, Pbuf, 1280, 2560, 320);
    gemm_reduce_kernel<<<(B*1280/4+255)/256, 256>>>(Pbuf, layer_b2, out_x, B*1280/4, 1280/4, 8, 0);

    // 3) mlp: relu(x@W1+b1)@W2+b2 -> out_px
    gemm_tc_kernel<<<dim3(80, 4), 256>>>(out_x, mlp_w1, Pbuf, 2560, 1280, 320);
    gemm_reduce_kernel<<<(B*2560/4+255)/256, 256>>>(Pbuf, mlp_b1, hbuf, B*2560/4, 2560/4, 4, 1);
    gemm_tc_kernel<<<dim3(4, 16), 256>>>(hbuf, mlp_w2, Pbuf, 128, 2560, 160);
    gemm_reduce_kernel<<<(B*128/4+255)/256, 256>>>(Pbuf, mlp_b2, out_px, B*128/4, 128/4, 16, 0);

    // 4) multimodal standardize (second pass is identity, skipped)
    std_ab_kernel<<<1280, 128>>>(modal_a, modal_b, cross);

    // 5) feat_encoder + fused LN
    gemm_tc_kernel<<<dim3(32, 8), 256>>>(cross, fe_w1, Pbuf, 1024, 1280, 160);
    gemm_reduce_kernel<<<(B*1024/4+255)/256, 256>>>(Pbuf, nullptr, tbuf, B*1024/4, 1024/4, 8, 1);
    gemm_tc_kernel<<<dim3(4, 8), 256>>>(tbuf, fe_w2, Pbuf, 128, 1024, 128);
    reduce_ln_kernel<<<B, 128>>>(Pbuf, fe_b2, lnf_g, lnf_b, out_pf, 8);
}

// round 6
// speedup vs baseline: 1.5985x; 1.1120x over previous
#include <cuda_runtime.h>
#include <cuda_bf16.h>
#include <cstdint>

#define B 128
#define L 1024
#define E 1280
#define E4 (E/4)     // 320
#define H 128
#define NCH 16
#define CHROWS (L/NCH) // 64

// ---------------- scratch ------------------------------------------------------
__device__ float g_pool_part[B * NCH * E];
__device__ float g_xpool[B * E];
__device__ float g_h[B * 2560];
__device__ float g_P1[4 * B * 2560];   // split-K partials, big GEMMs (reused)
__device__ float g_P2[8 * B * 1280];
__device__ float g_P4[16 * B * 128];
__device__ float g_cross[B * 1280];
__device__ float g_Pf[8 * B * 1024];
__device__ float g_Pf2[8 * B * 128];

// ---------------- pooling ----------------------------------------------------
__global__ void pool_partial_kernel(const float* __restrict__ esm,
                                    const int* __restrict__ vlens) {
    int b = blockIdx.x;
    int c = blockIdx.y;
    int t = threadIdx.x;            // 320 threads, one float4 each
    int len = vlens[b] + 2;
    int r0 = c * CHROWS;
    int r1 = min(r0 + CHROWS, len);
    float4 s = make_float4(0.f, 0.f, 0.f, 0.f);
    const float4* base = (const float4*)(esm + (size_t)b * L * E);
    for (int r = r0; r < r1; ++r) {
        float4 v = base[(size_t)r * E4 + t];
        s.x += v.x; s.y += v.y; s.z += v.z; s.w += v.w;
    }
    ((float4*)g_pool_part)[((size_t)b * NCH + c) * E4 + t] = s;
}

__global__ void pool_reduce_kernel(const int* __restrict__ vlens) {
    int b = blockIdx.x;
    int t = threadIdx.x;            // 320 threads
    float inv = 1.0f / (float)(vlens[b] + 2);
    float4 s = make_float4(0.f, 0.f, 0.f, 0.f);
    for (int c = 0; c < NCH; ++c) {
        float4 v = ((const float4*)g_pool_part)[((size_t)b * NCH + c) * E4 + t];
        s.x += v.x; s.y += v.y; s.z += v.z; s.w += v.w;
    }
    s.x *= inv; s.y *= inv; s.z *= inv; s.w *= inv;
    ((float4*)g_xpool)[(size_t)b * E4 + t] = s;
}

// ---------------- tf32 tensor-core GEMM, double-buffered ----------------------
// P[ks][128][N] partial = A[128, k0:k0+Kc] @ W[k0:k0+Kc, N].
// A may itself be a composed split-K partial stack: A = act(bias + sum_KSIN slabs).
__device__ __forceinline__ unsigned f2tf(float x) {
    unsigned r; asm("cvt.rna.tf32.f32 %0, %1;" : "=r"(r) : "f"(x)); return r;
}

template<int KSIN>
__device__ __forceinline__ float4 load_composeA(const float* __restrict__ A,
                                                int row, int K, int kk,
                                                const float* __restrict__ a_bias,
                                                int a_relu)
{
    size_t base = (size_t)row * K + kk;
    float4 s = *(const float4*)(A + base);
    if (KSIN > 1) {
        size_t slab = (size_t)128 * K;
        #pragma unroll
        for (int ss = 1; ss < KSIN; ++ss) {
            float4 v = *(const float4*)(A + (size_t)ss * slab + base);
            s.x += v.x; s.y += v.y; s.z += v.z; s.w += v.w;
        }
        if (a_bias) {
            float4 bv = *(const float4*)(a_bias + kk);
            s.x += bv.x; s.y += bv.y; s.z += bv.z; s.w += bv.w;
        }
        if (a_relu) {
            s.x = fmaxf(s.x, 0.f); s.y = fmaxf(s.y, 0.f);
            s.z = fmaxf(s.z, 0.f); s.w = fmaxf(s.w, 0.f);
        }
    }
    return s;
}

template<int KSIN>
__global__ __launch_bounds__(256, 2) void gemm_tc_kernel(
    const float* __restrict__ A, const float* __restrict__ W,
    float* __restrict__ P, const float* __restrict__ a_bias,
    int N, int K, int Kc, int a_relu)
{
    __shared__ unsigned As[2][128 * 36];
    __shared__ unsigned Bs[2][4 * 32 * 8];

    int tid = threadIdx.x;
    int warp = tid >> 5;
    int lane = tid & 31;
    int wm = warp >> 1;
    int wn = warp & 1;
    int g  = lane >> 2;
    int tg = lane & 3;

    int n_blk = blockIdx.x * 32;
    int k0 = blockIdx.y * Kc;

    int arow0 = tid >> 3;
    int akq   = (tid & 7) * 4;
    int wk    = tid >> 3;
    int wn4   = (tid & 7) * 4;
    int wchunk = wn4 >> 3;
    int woff   = wn4 & 7;

    float acc[2][2][4];
    #pragma unroll
    for (int mt = 0; mt < 2; ++mt)
        #pragma unroll
        for (int nt = 0; nt < 2; ++nt)
            #pragma unroll
            for (int i = 0; i < 4; ++i) acc[mt][nt][i] = 0.f;

    float4 av[4]; float4 wv;

    // prologue: load + store tile 0
    #pragma unroll
    for (int j = 0; j < 4; ++j)
        av[j] = load_composeA<KSIN>(A, arow0 + 32 * j, K, k0 + akq, a_bias, a_relu);
    wv = *(const float4*)(W + (size_t)(k0 + wk) * N + n_blk + wn4);
    #pragma unroll
    for (int j = 0; j < 4; ++j) {
        unsigned* ap = &As[0][(arow0 + 32 * j) * 36 + akq];
        ap[0] = f2tf(av[j].x); ap[1] = f2tf(av[j].y);
        ap[2] = f2tf(av[j].z); ap[3] = f2tf(av[j].w);
    }
    {
        unsigned* bp = &Bs[0][wchunk * 256 + wk * 8 + woff];
        bp[0] = f2tf(wv.x); bp[1] = f2tf(wv.y);
        bp[2] = f2tf(wv.z); bp[3] = f2tf(wv.w);
    }

    int niter = Kc >> 5;
    int buf = 0;
    for (int it = 0; it < niter; ++it) {
        __syncthreads();
        bool has_next = (it + 1 < niter);
        if (has_next) {
            int kt = k0 + (it + 1) * 32;
            #pragma unroll
            for (int j = 0; j < 4; ++j)
                av[j] = load_composeA<KSIN>(A, arow0 + 32 * j, K, kt + akq, a_bias, a_relu);
            wv = *(const float4*)(W + (size_t)(kt + wk) * N + n_blk + wn4);
        }

        const unsigned* Ab = As[buf];
        const unsigned* Bb = Bs[buf];
        #pragma unroll
        for (int ks = 0; ks < 4; ++ks) {
            int k = ks * 8;
            unsigned a[2][4], bf[2][2];
            #pragma unroll
            for (int mt = 0; mt < 2; ++mt) {
                int r = wm * 32 + mt * 16 + g;
                a[mt][0] = Ab[r * 36 + k + tg];
                a[mt][1] = Ab[(r + 8) * 36 + k + tg];
                a[mt][2] = Ab[r * 36 + k + tg + 4];
                a[mt][3] = Ab[(r + 8) * 36 + k + tg + 4];
            }
            #pragma unroll
            for (int nt = 0; nt < 2; ++nt) {
                int c = wn * 2 + nt;
                bf[nt][0] = Bb[c * 256 + (k + tg) * 8 + g];
                bf[nt][1] = Bb[c * 256 + (k + tg + 4) * 8 + g];
            }
            #pragma unroll
            for (int mt = 0; mt < 2; ++mt)
                #pragma unroll
                for (int nt = 0; nt < 2; ++nt) {
                    asm volatile(
                        "mma.sync.aligned.m16n8k8.row.col.f32.tf32.tf32.f32 "
                        "{%0,%1,%2,%3}, {%4,%5,%6,%7}, {%8,%9}, {%0,%1,%2,%3};\n"
                        : "+f"(acc[mt][nt][0]), "+f"(acc[mt][nt][1]),
                          "+f"(acc[mt][nt][2]), "+f"(acc[mt][nt][3])
                        : "r"(a[mt][0]), "r"(a[mt][1]), "r"(a[mt][2]), "r"(a[mt][3]),
                          "r"(bf[nt][0]), "r"(bf[nt][1]));
                }
        }

        if (has_next) {
            unsigned* Aw = As[buf ^ 1];
            unsigned* Bw = Bs[buf ^ 1];
            #pragma unroll
            for (int j = 0; j < 4; ++j) {
                unsigned* ap = &Aw[(arow0 + 32 * j) * 36 + akq];
                ap[0] = f2tf(av[j].x); ap[1] = f2tf(av[j].y);
                ap[2] = f2tf(av[j].z); ap[3] = f2tf(av[j].w);
            }
            unsigned* bp = &Bw[wchunk * 256 + wk * 8 + woff];
            bp[0] = f2tf(wv.x); bp[1] = f2tf(wv.y);
            bp[2] = f2tf(wv.z); bp[3] = f2tf(wv.w);
        }
        buf ^= 1;
    }

    float* dst = P + (size_t)blockIdx.y * 128 * N + n_blk;
    #pragma unroll
    for (int mt = 0; mt < 2; ++mt) {
        int row = wm * 32 + mt * 16 + g;
        #pragma unroll
        for (int nt = 0; nt < 2; ++nt) {
            int nloc = wn * 16 + nt * 8 + tg * 2;
            *(float2*)(dst + (size_t)row * N + nloc) =
                make_float2(acc[mt][nt][0], acc[mt][nt][1]);
            *(float2*)(dst + (size_t)(row + 8) * N + nloc) =
                make_float2(acc[mt][nt][2], acc[mt][nt][3]);
        }
    }
}

// ---------------- split-K reduce, templated for full ILP ----------------------
template<int KS>
__global__ void reduce_kernel(const float* __restrict__ P,
                              const float* __restrict__ bias,
                              float* __restrict__ out,
                              int MN4, int N4, int relu)
{
    int i = blockIdx.x * 256 + threadIdx.x;
    if (i >= MN4) return;
    float4 v[KS];
    #pragma unroll
    for (int s = 0; s < KS; ++s) v[s] = ((const float4*)P)[(size_t)s * MN4 + i];
    float4 a = v[0];
    #pragma unroll
    for (int s = 1; s < KS; ++s) {
        a.x += v[s].x; a.y += v[s].y; a.z += v[s].z; a.w += v[s].w;
    }
    if (bias) {
        float4 bv = ((const float4*)bias)[i % N4];
        a.x += bv.x; a.y += bv.y; a.z += bv.z; a.w += bv.w;
    }
    if (relu) {
        a.x = fmaxf(a.x, 0.f); a.y = fmaxf(a.y, 0.f);
        a.z = fmaxf(a.z, 0.f); a.w = fmaxf(a.w, 0.f);
    }
    ((float4*)out)[i] = a;
}

// ---------------- block reduce helper -----------------------------------------
__device__ __forceinline__ float block_reduce_128(float v, float* sh) {
    int t = threadIdx.x;
    sh[t] = v;
    __syncthreads();
    #pragma unroll
    for (int s = 64; s > 0; s >>= 1) {
        if (t < s) sh[t] += sh[t + s];
        __syncthreads();
    }
    float r = sh[0];
    __syncthreads();
    return r;
}

// ---------------- fused standardize of modal_a | modal_b ----------------------
__global__ void std_ab_kernel(const float* __restrict__ a,
                              const float* __restrict__ bsrc,
                              float* __restrict__ cross)
{
    __shared__ float sh[128];
    int col = blockIdx.x;           // 0..1279
    int t = threadIdx.x;            // 128 rows
    const float* src; int nc, c;
    if (col < 512) { src = a;    nc = 512; c = col; }
    else           { src = bsrc; nc = 768; c = col - 512; }
    float v = src[(size_t)t * nc + c];
    float mean = block_reduce_128(v, sh) * (1.0f / 128.0f);
    float d = v - mean;
    float var = block_reduce_128(d * d, sh) * (1.0f / 127.0f);  // ddof=1
    cross[(size_t)t * 1280 + col] = d * rsqrtf(var);
}

// ---------------- fused split-K reduce + bias + layernorm ---------------------
__global__ void reduce_ln_kernel(const float* __restrict__ P,
                                 const float* __restrict__ bias,
                                 const float* __restrict__ g,
                                 const float* __restrict__ bta,
                                 float* __restrict__ out)
{
    __shared__ float sh[128];
    int row = blockIdx.x;
    int t = threadIdx.x;            // H = 128 cols
    float s = bias[t];
    #pragma unroll
    for (int ks = 0; ks < 8; ++ks)
        s += P[(size_t)ks * (B * H) + (size_t)row * H + t];
    float mean = block_reduce_128(s, sh) * (1.0f / 128.0f);
    float d = s - mean;
    float var = block_reduce_128(d * d, sh) * (1.0f / 128.0f);
    out[(size_t)row * H + t] = d * rsqrtf(var + 1e-5f) * g[t] + bta[t];
}

// ---------------- launch ------------------------------------------------------
extern "C" void kernel_launch(void* const* d_in, const int* in_sizes, int n_in,
                              void* d_out, int out_size)
{
    const float* esm      = (const float*)d_in[0];
    const int*   vlens    = (const int*)  d_in[1];
    const float* modal_a  = (const float*)d_in[2];
    const float* modal_b  = (const float*)d_in[3];
    const float* layer_w1 = (const float*)d_in[4];
    const float* layer_b1 = (const float*)d_in[5];
    const float* layer_w2 = (const float*)d_in[6];
    const float* layer_b2 = (const float*)d_in[7];
    const float* mlp_w1   = (const float*)d_in[8];
    const float* mlp_b1   = (const float*)d_in[9];
    const float* mlp_w2   = (const float*)d_in[10];
    const float* mlp_b2   = (const float*)d_in[11];
    const float* fe_w1    = (const float*)d_in[12];
    const float* fe_w2    = (const float*)d_in[13];
    const float* fe_b2    = (const float*)d_in[14];
    const float* lnf_g    = (const float*)d_in[15];
    const float* lnf_b    = (const float*)d_in[16];

    float* out_x  = (float*)d_out;
    float* out_px = out_x + B * E;
    float* out_pf = out_px + B * H;

    float* xpool = nullptr; cudaGetSymbolAddress((void**)&xpool, g_xpool);
    float* hbuf  = nullptr; cudaGetSymbolAddress((void**)&hbuf,  g_h);
    float* P1    = nullptr; cudaGetSymbolAddress((void**)&P1,    g_P1);
    float* P2    = nullptr; cudaGetSymbolAddress((void**)&P2,    g_P2);
    float* P4    = nullptr; cudaGetSymbolAddress((void**)&P4,    g_P4);
    float* cross = nullptr; cudaGetSymbolAddress((void**)&cross, g_cross);
    float* Pf    = nullptr; cudaGetSymbolAddress((void**)&Pf,    g_Pf);
    float* Pf2   = nullptr; cudaGetSymbolAddress((void**)&Pf2,   g_Pf2);

    // ---- fork a side stream for the independent multimodal branch ----
    cudaStream_t s2;
    cudaStreamCreate(&s2);                 // host resource; leaked (few calls only)
    cudaEvent_t ev_fork, ev_join;
    cudaEventCreateWithFlags(&ev_fork, cudaEventDisableTiming);
    cudaEventCreateWithFlags(&ev_join, cudaEventDisableTiming);

    cudaEventRecord(ev_fork, 0);
    cudaStreamWaitEvent(s2, ev_fork, 0);

    // ---- branch B (multimodal) on s2, overlaps pool + main chain ----
    std_ab_kernel<<<1280, 128, 0, s2>>>(modal_a, modal_b, cross);
    gemm_tc_kernel<1><<<dim3(32, 8), 256, 0, s2>>>(cross, fe_w1, Pf, nullptr,
                                                   1024, 1280, 160, 0);
    gemm_tc_kernel<8><<<dim3(4, 8), 256, 0, s2>>>(Pf, fe_w2, Pf2, nullptr,
                                                  128, 1024, 128, 1);
    reduce_ln_kernel<<<B, 128, 0, s2>>>(Pf2, fe_b2, lnf_g, lnf_b, out_pf);
    cudaEventRecord(ev_join, s2);

    // ---- main chain on default stream ----
    pool_partial_kernel<<<dim3(B, NCH), 320>>>(esm, vlens);
    pool_reduce_kernel<<<B, 320>>>(vlens);

    // layers: relu(x@W1+b1)@W2+b2 -> out_x
    gemm_tc_kernel<1><<<dim3(80, 4), 256>>>(xpool, layer_w1, P1, nullptr,
                                            2560, 1280, 320, 0);
    reduce_kernel<4><<<320, 256>>>(P1, layer_b1, hbuf, B*2560/4, 2560/4, 1);
    gemm_tc_kernel<1><<<dim3(40, 8), 256>>>(hbuf, layer_w2, P2, nullptr,
                                            1280, 2560, 320, 0);
    reduce_kernel<8><<<160, 256>>>(P2, layer_b2, out_x, B*1280/4, 1280/4, 0);

    // mlp: relu(out_x@W1+b1)@W2+b2 -> out_px  (final reduce fused into gemm A-path)
    gemm_tc_kernel<1><<<dim3(80, 4), 256>>>(out_x, mlp_w1, P1, nullptr,
                                            2560, 1280, 320, 0);
    gemm_tc_kernel<4><<<dim3(4, 16), 256>>>(P1, mlp_w2, P4, mlp_b1,
                                            128, 2560, 160, 1);
    reduce_kernel<16><<<16, 256>>>(P4, mlp_b2, out_px, B*128/4, 128/4, 0);

    // ---- join ----
    cudaStreamWaitEvent(0, ev_join, 0);
}